// round 8
// baseline (speedup 1.0000x reference)
#include <cuda_runtime.h>
#include <cuda_bf16.h>
#include <stdint.h>

#define NUM_ROWS 16384
#define HDIM     2048
#define KSEL     4
#define NEXP     64
#define NTOT     (NUM_ROWS * KSEL)   /* 65536 expanded slots */
#define NCHUNK   256
#define CHUNK    (NTOT / NCHUNK)     /* 256 items per chunk */
#define NWARP    (CHUNK / 32)        /* 8 warps per chunk block */

/* output layout (floats) */
#define X_OFF   0
#define RI_OFF  ((size_t)NTOT * HDIM)                 /* 134217728 */
#define CNT_OFF (RI_OFF + NTOT)                        /* +65536 */
#define SC_OFF  (CNT_OFF + NEXP)                       /* +64 */

/* scratch (no cudaMalloc allowed) */
__device__ int g_chunkCounts[NCHUNK * NEXP];  /* K1: counts; K2: stable bases */
__device__ int g_rank[NTOT];                  /* intra-chunk stable rank      */

/* ---- K1: per-chunk histogram + intra-chunk stable rank ---- */
__global__ void __launch_bounds__(CHUNK) k_rank(const int* __restrict__ eidx) {
    __shared__ int shcnt[NWARP][NEXP];
    int t = threadIdx.x;
    int c = blockIdx.x;
    int w = t >> 5, lane = t & 31;

    for (int j = t; j < NWARP * NEXP; j += CHUNK)
        ((int*)shcnt)[j] = 0;
    __syncthreads();

    int i = c * CHUNK + t;
    int e = eidx[i];
    unsigned m = __match_any_sync(0xffffffffu, e);
    int rank = __popc(m & ((1u << lane) - 1));
    if (rank == 0) shcnt[w][e] = __popc(m);
    __syncthreads();

    int off = 0;
#pragma unroll
    for (int w2 = 0; w2 < NWARP; ++w2)
        if (w2 < w) off += shcnt[w2][e];
    g_rank[i] = off + rank;

    if (t < NEXP) {
        int s = 0;
#pragma unroll
        for (int w2 = 0; w2 < NWARP; ++w2) s += shcnt[w2][t];
        g_chunkCounts[c * NEXP + t] = s;
    }
}

/* ---- K2: parallel scan -> stable per-chunk/per-expert bases + counts ---- */
#define GRP 16
#define CPG (NCHUNK / GRP)   /* 16 chunks per group */
__global__ void __launch_bounds__(1024) k_scan(float* __restrict__ out) {
#if __CUDA_ARCH__ >= 900
    cudaGridDependencySynchronize();
#endif
    __shared__ int tot[NEXP];
    __shared__ int offs[NEXP];
    int t = threadIdx.x;
    int e = t >> 4;           /* expert 0..63 */
    int g = t & (GRP - 1);    /* chunk-group 0..15 */

    int v[CPG];
    int partial = 0;
#pragma unroll
    for (int j = 0; j < CPG; ++j) {
        v[j] = g_chunkCounts[(g * CPG + j) * NEXP + e];
        partial += v[j];
    }

    int inc = partial;
#pragma unroll
    for (int d = 1; d < GRP; d <<= 1) {
        int y = __shfl_up_sync(0xffffffffu, inc, d, GRP);
        if (g >= d) inc += y;
    }
    if (g == GRP - 1) tot[e] = inc;
    __syncthreads();

    if (t == 0) {
        int run = 0;
        for (int j = 0; j < NEXP; ++j) { offs[j] = run; run += tot[j]; }
    }
    __syncthreads();
    if (t < NEXP) out[CNT_OFF + t] = (float)tot[t];

    int run = offs[e] + (inc - partial);   /* exclusive base for this group */
#pragma unroll
    for (int j = 0; j < CPG; ++j) {
        g_chunkCounts[(g * CPG + j) * NEXP + e] = run;
        run += v[j];
    }
}

/* ---- K3: big gather copy + final dest resolve + small outputs ----
 * The x loads (independent of the setup kernels' results) are issued BEFORE
 * the grid-dependency sync, so first-wave blocks stream x while k_rank/k_scan
 * finish. Only 2 front-batched LDG.128 per thread (MLP_p1=2) to stay under
 * the cross-CTA L1tex-queue contention knee.
 */
__global__ void __launch_bounds__(256) k_copy(const float* __restrict__ x,
                                              const int* __restrict__ eidx,
                                              const float* __restrict__ scale,
                                              float* __restrict__ out) {
    int i = blockIdx.x;          /* expanded slot 0..NTOT-1 */
    int src = i >> 2;
    int t = threadIdx.x;

    const float4* __restrict__ s = (const float4*)(x + (size_t)src * HDIM);
    float4 v0 = s[t];
    float4 v1 = s[t + 256];

#if __CUDA_ARCH__ >= 900
    cudaGridDependencySynchronize();
#endif

    int e = __ldg(eidx + i);
    int d = g_chunkCounts[(i >> 8) * NEXP + e] + g_rank[i];

    float4* __restrict__ o = (float4*)(out + X_OFF + (size_t)d * HDIM);
    o[t]       = v0;
    o[t + 256] = v1;

    if (t == 0) {
        out[RI_OFF + i] = (float)d;
        out[SC_OFF + d] = scale[src];
    }
}

extern "C" void kernel_launch(void* const* d_in, const int* in_sizes, int n_in,
                              void* d_out, int out_size) {
    const float* x     = (const float*)d_in[0];
    const int*   eidx  = (const int*)d_in[1];
    const float* scale = (const float*)d_in[2];
    float* out = (float*)d_out;

    /* K1: plain launch */
    k_rank<<<NCHUNK, CHUNK>>>(eidx);

    /* K2, K3: programmatic dependent launches; consumers do independent work
     * before cudaGridDependencySynchronize(). */
    cudaLaunchAttribute attr[1];
    attr[0].id = cudaLaunchAttributeProgrammaticStreamSerialization;
    attr[0].val.programmaticStreamSerializationAllowed = 1;

    {
        cudaLaunchConfig_t cfg = {};
        cfg.gridDim  = dim3(1, 1, 1);
        cfg.blockDim = dim3(1024, 1, 1);
        cfg.dynamicSmemBytes = 0;
        cfg.stream = 0;
        cfg.attrs = attr;
        cfg.numAttrs = 1;
        cudaLaunchKernelEx(&cfg, k_scan, out);
    }
    {
        cudaLaunchConfig_t cfg = {};
        cfg.gridDim  = dim3(NTOT, 1, 1);
        cfg.blockDim = dim3(256, 1, 1);
        cfg.dynamicSmemBytes = 0;
        cfg.stream = 0;
        cfg.attrs = attr;
        cfg.numAttrs = 1;
        cudaLaunchKernelEx(&cfg, k_copy, x, eidx, scale, out);
    }
}

// round 9
// speedup vs baseline: 1.2158x; 1.2158x over previous
#include <cuda_runtime.h>
#include <cuda_bf16.h>
#include <stdint.h>

#define NUM_ROWS 16384
#define HDIM     2048
#define KSEL     4
#define NEXP     64
#define NTOT     (NUM_ROWS * KSEL)   /* 65536 expanded slots */
#define NCHUNK   256
#define CHUNK    (NTOT / NCHUNK)     /* 256 items per chunk */
#define NWARP    (CHUNK / 32)        /* 8 warps per chunk block */

/* output layout (floats) */
#define X_OFF   0
#define RI_OFF  ((size_t)NTOT * HDIM)                 /* 134217728 */
#define CNT_OFF (RI_OFF + NTOT)                        /* +65536 */
#define SC_OFF  (CNT_OFF + NEXP)                       /* +64 */

/* scratch (no cudaMalloc allowed) */
__device__ int g_chunkCounts[NCHUNK * NEXP];  /* counts -> stable bases */
__device__ int g_rank[NTOT];                  /* intra-chunk stable rank */
__device__ unsigned g_ticket = 0;             /* monotonic across replays */

/* ---- K1: histogram + stable rank; LAST block also does the scan ----
 * No spinning: non-last blocks exit after their histogram; the last-arriving
 * block (ticket test) converts counts -> stable bases and emits expert counts.
 */
__global__ void __launch_bounds__(CHUNK) k_setup(const int* __restrict__ eidx,
                                                 float* __restrict__ out) {
    __shared__ int shcnt[NWARP][NEXP];
    __shared__ int offs[NEXP];
    __shared__ int s_last;

    int t = threadIdx.x;
    int c = blockIdx.x;
    int w = t >> 5, lane = t & 31;

    for (int j = t; j < NWARP * NEXP; j += CHUNK)
        ((int*)shcnt)[j] = 0;
    __syncthreads();

    int i = c * CHUNK + t;
    int e = eidx[i];
    unsigned m = __match_any_sync(0xffffffffu, e);
    int rank = __popc(m & ((1u << lane) - 1));
    if (rank == 0) shcnt[w][e] = __popc(m);
    __syncthreads();

    int off = 0;
#pragma unroll
    for (int w2 = 0; w2 < NWARP; ++w2)
        if (w2 < w) off += shcnt[w2][e];
    g_rank[i] = off + rank;

    if (t < NEXP) {
        int s = 0;
#pragma unroll
        for (int w2 = 0; w2 < NWARP; ++w2) s += shcnt[w2][t];
        g_chunkCounts[c * NEXP + t] = s;
    }
    __threadfence();
    __syncthreads();

    if (t == 0) {
        unsigned ticket = atomicAdd(&g_ticket, 1u);
        s_last = ((ticket % NCHUNK) == NCHUNK - 1);
    }
    __syncthreads();
    if (!s_last) return;

    /* ---- last block: scan (all other blocks' counts are visible) ---- */
    __threadfence();
    /* thread layout: expert e2 = t>>2 (0..63), group g2 = t&3 owns 64 chunks */
    int e2 = t >> 2;
    int g2 = t & 3;
    int partial = 0;
#pragma unroll 8
    for (int j = 0; j < 64; ++j)
        partial += g_chunkCounts[(g2 * 64 + j) * NEXP + e2];

    int inc = partial;
#pragma unroll
    for (int d = 1; d < 4; d <<= 1) {
        int y = __shfl_up_sync(0xffffffffu, inc, d, 4);
        if (g2 >= d) inc += y;
    }
    int etotal = __shfl_sync(0xffffffffu, inc, 3, 4);
    if (g2 == 3) { shcnt[0][e2] = inc; }   /* reuse smem: totals */
    __syncthreads();
    if (t == 0) {
        int run = 0;
        for (int j = 0; j < NEXP; ++j) { offs[j] = run; run += shcnt[0][j]; }
    }
    __syncthreads();
    if (t < NEXP) out[CNT_OFF + t] = (float)shcnt[0][t];
    (void)etotal;

    int run = offs[e2] + (inc - partial);   /* exclusive base for this group */
#pragma unroll 8
    for (int j = 0; j < 64; ++j) {
        int idx = (g2 * 64 + j) * NEXP + e2;
        int v = g_chunkCounts[idx];
        g_chunkCounts[idx] = run;
        run += v;
    }
}

/* ---- K2: big gather copy + final dest resolve + small outputs ----
 * PROVEN shape: 128 threads, 1 row per block, interleaved load->store. */
__global__ void __launch_bounds__(128) k_copy(const float* __restrict__ x,
                                              const int* __restrict__ eidx,
                                              const float* __restrict__ scale,
                                              float* __restrict__ out) {
#if __CUDA_ARCH__ >= 900
    cudaGridDependencySynchronize();
#endif
    int i = blockIdx.x;          /* expanded slot 0..NTOT-1 */
    int e = __ldg(eidx + i);
    int d = g_chunkCounts[(i >> 8) * NEXP + e] + g_rank[i];
    int src = i >> 2;

    const float4* __restrict__ s = (const float4*)(x + (size_t)src * HDIM);
    float4* __restrict__ o = (float4*)(out + X_OFF + (size_t)d * HDIM);
#pragma unroll
    for (int j = 0; j < 4; ++j) {
        int idx = threadIdx.x + j * 128;   /* 512 float4 per row */
        o[idx] = s[idx];
    }
    if (threadIdx.x == 0) {
        out[RI_OFF + i] = (float)d;
        out[SC_OFF + d] = scale[src];
    }
}

extern "C" void kernel_launch(void* const* d_in, const int* in_sizes, int n_in,
                              void* d_out, int out_size) {
    const float* x     = (const float*)d_in[0];
    const int*   eidx  = (const int*)d_in[1];
    const float* scale = (const float*)d_in[2];
    float* out = (float*)d_out;

    k_setup<<<NCHUNK, CHUNK>>>(eidx, out);

    cudaLaunchAttribute attr[1];
    attr[0].id = cudaLaunchAttributeProgrammaticStreamSerialization;
    attr[0].val.programmaticStreamSerializationAllowed = 1;

    cudaLaunchConfig_t cfg = {};
    cfg.gridDim  = dim3(NTOT, 1, 1);
    cfg.blockDim = dim3(128, 1, 1);
    cfg.dynamicSmemBytes = 0;
    cfg.stream = 0;
    cfg.attrs = attr;
    cfg.numAttrs = 1;
    cudaLaunchKernelEx(&cfg, k_copy, x, eidx, scale, out);
}